// round 6
// baseline (speedup 1.0000x reference)
#include <cuda_runtime.h>
#include <cuda_bf16.h>
#include <cuda_fp8.h>
#include <cstdint>

#define N_SRC 4096
#define D     256
#define TOT   8192
#define TILE  128
#define NT    (TOT / TILE)     // 64
#define HALF_NT (NT / 2)       // 32
#define CKB   128              // K-chunk bytes per row (128 fp8)
#define NC    2                // 2 chunks of K=128 fp8
#define ROWB  144              // smem row stride: 128B data + 16B pad, conflict-free
#define MATB  (TILE * ROWB)    // 18432
#define STAGEB (2 * MATB)      // 36864
#define SQ_OFF (2 * STAGEB)    // 73728
#define SMEM_TOTAL (SQ_OFF + 2 * TILE * 4)   // 74752

// -------- device scratch --------
__device__ uint8_t g_q[(size_t)TOT * D];   // e4m3-quantized data
__device__ float  g_sq[TOT];
__device__ double g_acc;

// ---------------------------------------------------------------------------
// Kernel 1: fp32 -> e4m3 + per-row sumsq of the QUANTIZED values. Warp/row.
// ---------------------------------------------------------------------------
__global__ void prep_kernel(const float* __restrict__ src,
                            const float* __restrict__ tgt) {
    int lane = threadIdx.x & 31;
    int warp = threadIdx.x >> 5;
    int row  = blockIdx.x * 8 + warp;
    const float* base = (row < N_SRC) ? (src + (size_t)row * D)
                                      : (tgt + (size_t)(row - N_SRC) * D);
    float4 v0 = ((const float4*)base)[lane * 2];
    float4 v1 = ((const float4*)base)[lane * 2 + 1];
    float v[8] = {v0.x, v0.y, v0.z, v0.w, v1.x, v1.y, v1.z, v1.w};

    uint8_t qb[8];
    float s = 0.f;
    #pragma unroll
    for (int i = 0; i < 8; i++) {
        __nv_fp8_e4m3 q(v[i]);
        qb[i] = *(uint8_t*)&q;
        float f = float(q);
        s += f * f;
    }
    uint2 o;
    o.x = (uint32_t)qb[0] | ((uint32_t)qb[1] << 8) |
          ((uint32_t)qb[2] << 16) | ((uint32_t)qb[3] << 24);
    o.y = (uint32_t)qb[4] | ((uint32_t)qb[5] << 8) |
          ((uint32_t)qb[6] << 16) | ((uint32_t)qb[7] << 24);
    ((uint2*)(g_q + (size_t)row * D))[lane] = o;

    #pragma unroll
    for (int o2 = 16; o2; o2 >>= 1) s += __shfl_xor_sync(0xFFFFFFFFu, s, o2);
    if (lane == 0) g_sq[row] = s;
    if (row == 0 && lane == 0) g_acc = 0.0;
}

// ---------------------------------------------------------------------------
// mma helpers
// ---------------------------------------------------------------------------
__device__ __forceinline__ void ldsm_x4(uint32_t& r0, uint32_t& r1,
                                        uint32_t& r2, uint32_t& r3,
                                        uint32_t addr) {
    asm volatile(
        "ldmatrix.sync.aligned.m8n8.x4.shared.b16 {%0,%1,%2,%3}, [%4];"
        : "=r"(r0), "=r"(r1), "=r"(r2), "=r"(r3)
        : "r"(addr));
}

__device__ __forceinline__ void mma_fp8(float* c, const uint32_t* a,
                                        uint32_t b0, uint32_t b1) {
    asm volatile(
        "mma.sync.aligned.m16n8k32.row.col.f32.e4m3.e4m3.f32 "
        "{%0,%1,%2,%3}, {%4,%5,%6,%7}, {%8,%9}, {%0,%1,%2,%3};"
        : "+f"(c[0]), "+f"(c[1]), "+f"(c[2]), "+f"(c[3])
        : "r"(a[0]), "r"(a[1]), "r"(a[2]), "r"(a[3]), "r"(b0), "r"(b1));
}

__device__ __forceinline__ void cp16(uint32_t dst, const void* src) {
    asm volatile("cp.async.cg.shared.global [%0], [%1], 16;"
                 :: "r"(dst), "l"(src) : "memory");
}

__device__ __forceinline__ float ex2f(float x) {
    float y;
    asm("ex2.approx.ftz.f32 %0, %1;" : "=f"(y) : "f"(x));
    return y;
}

// ---------------------------------------------------------------------------
// Kernel 2: one CTA per 128x128 tile (upper block triangle), 8 warps (32x64
// warp tiles), fp8 mma.sync, cp.async 2-stage K-chunk pipeline, 2 CTAs/SM.
// Fragment note: fp8 m16n8k32 fragments == bf16 m16n8k16 fragments with each
// "b16 element" being a packed fp8 pair, so the ldmatrix addressing below is
// identical to the validated bf16 version.
// ---------------------------------------------------------------------------
__global__ void __launch_bounds__(256, 2)
mmd_kernel() {
    const int bi = blockIdx.x;
    const int bj = blockIdx.y;
    if (bj < bi) return;

    extern __shared__ __align__(128) char smem[];
    uint32_t sb = (uint32_t)__cvta_generic_to_shared(smem);

    const int tid  = threadIdx.x;
    const int lane = tid & 31;
    const int warp = tid >> 5;
    const int wm   = warp & 3;
    const int wn   = warp >> 2;

    float* sqA = (float*)(smem + SQ_OFF);
    float* sqB = sqA + TILE;
    if (tid < TILE)        sqA[tid] = g_sq[bi * TILE + tid];
    else                   sqB[tid - TILE] = g_sq[bj * TILE + (tid - TILE)];

    const uint8_t* Ag = g_q + (size_t)bi * TILE * D;
    const uint8_t* Bg = g_q + (size_t)bj * TILE * D;

    // ---- cp.async chunk loader: 2048 x 16B per chunk, 8 per thread ----
    auto load_chunk = [&](int c) {
        const int stage = c & 1;
        #pragma unroll
        for (int v = 0; v < 8; v++) {
            int u   = v * 256 + tid;      // 0..2047
            int mat = u >> 10;            // 0=A, 1=B
            int r   = (u >> 3) & 127;
            int vi  = u & 7;
            const uint8_t* g = (mat ? Bg : Ag) + (size_t)r * D + c * CKB + vi * 16;
            uint32_t dst = sb + stage * STAGEB + mat * MATB + r * ROWB + vi * 16;
            cp16(dst, g);
        }
    };

    // ---- ldmatrix addresses (byte offsets; "col" = fp8 pair = 2 bytes) ----
    uint32_t addrA[2];
    #pragma unroll
    for (int mt = 0; mt < 2; mt++) {
        int r = wm * 32 + mt * 16 + (lane & 15);
        int coff = (lane >> 4) * 8;
        addrA[mt] = sb + (uint32_t)(r * ROWB + coff * 2);
    }
    uint32_t addrB[4];
    #pragma unroll
    for (int nt4 = 0; nt4 < 4; nt4++) {
        int quad = lane >> 3;
        int r = wn * 64 + nt4 * 16 + (lane & 7) + ((quad & 2) ? 8 : 0);
        int coff = (quad & 1) * 8;
        addrB[nt4] = sb + MATB + (uint32_t)(r * ROWB + coff * 2);
    }

    float c[2][8][4];
    #pragma unroll
    for (int mt = 0; mt < 2; mt++)
        #pragma unroll
        for (int nt = 0; nt < 8; nt++)
            #pragma unroll
            for (int e = 0; e < 4; e++) c[mt][nt][e] = 0.f;

    // ---- prologue: prefetch both chunks ----
    load_chunk(0);
    asm volatile("cp.async.commit_group;" ::: "memory");
    load_chunk(1);
    asm volatile("cp.async.commit_group;" ::: "memory");

    // ---- mainloop over 2 K-chunks ----
    #pragma unroll
    for (int ch = 0; ch < NC; ch++) {
        asm volatile("cp.async.wait_group 1;" ::: "memory");
        __syncthreads();

        const uint32_t soff = (ch & 1) * STAGEB;
        #pragma unroll
        for (int kk = 0; kk < 4; kk++) {           // 4 x k32 per chunk
            uint32_t kb = soff + (uint32_t)kk * 32;
            uint32_t a[2][4];
            ldsm_x4(a[0][0], a[0][1], a[0][2], a[0][3], addrA[0] + kb);
            ldsm_x4(a[1][0], a[1][1], a[1][2], a[1][3], addrA[1] + kb);
            uint32_t b[4][4];
            #pragma unroll
            for (int nt4 = 0; nt4 < 4; nt4++)
                ldsm_x4(b[nt4][0], b[nt4][1], b[nt4][2], b[nt4][3],
                        addrB[nt4] + kb);
            #pragma unroll
            for (int mt = 0; mt < 2; mt++)
                #pragma unroll
                for (int nt4 = 0; nt4 < 4; nt4++) {
                    mma_fp8(c[mt][2 * nt4],     a[mt], b[nt4][0], b[nt4][1]);
                    mma_fp8(c[mt][2 * nt4 + 1], a[mt], b[nt4][2], b[nt4][3]);
                }
        }
        __syncthreads();
        asm volatile("cp.async.commit_group;" ::: "memory");
    }

    // ---- epilogue ----
    const float NEG_L2E_16 = -1.4426950408889634f / 16.0f;
    const int g = lane >> 2;
    const int q = lane & 3;
    float wgt = (((bi < HALF_NT) == (bj < HALF_NT)) ? 1.0f : -1.0f)
              * ((bi == bj) ? 1.0f : 2.0f);

    float acc = 0.f;
    #pragma unroll
    for (int mt = 0; mt < 2; mt++) {
        #pragma unroll
        for (int nt = 0; nt < 8; nt++) {
            #pragma unroll
            for (int e = 0; e < 4; e++) {
                int r    = wm * 32 + mt * 16 + g + ((e >> 1) << 3);
                int cidx = wn * 64 + nt * 8 + q * 2 + (e & 1);
                float l2 = sqA[r] + sqB[cidx] - 2.0f * c[mt][nt][e];
                float u  = ex2f(l2 * NEG_L2E_16);   // exp(-l2/16)
                float u2 = u * u, u4 = u2 * u2, u8 = u4 * u4, u16 = u8 * u8;
                acc += ((u + u2) + (u4 + u8)) + u16;
            }
        }
    }
    #pragma unroll
    for (int o = 16; o; o >>= 1) acc += __shfl_xor_sync(0xFFFFFFFFu, acc, o);
    if (lane == 0) atomicAdd(&g_acc, (double)(acc * wgt));
}

// ---------------------------------------------------------------------------
// Kernel 3: finalize scalar
// ---------------------------------------------------------------------------
__global__ void fin_kernel(float* out) {
    out[0] = (float)(g_acc * (1.0 / ((double)N_SRC * (double)N_SRC)));
}

extern "C" void kernel_launch(void* const* d_in, const int* in_sizes, int n_in,
                              void* d_out, int out_size) {
    const float* src = (const float*)d_in[0];
    const float* tgt = (const float*)d_in[1];
    float* out = (float*)d_out;

    cudaFuncSetAttribute(mmd_kernel,
                         cudaFuncAttributeMaxDynamicSharedMemorySize, SMEM_TOTAL);

    prep_kernel<<<TOT / 8, 256>>>(src, tgt);
    dim3 grid(NT, NT);
    mmd_kernel<<<grid, 256, SMEM_TOTAL>>>();
    fin_kernel<<<1, 1>>>(out);
}

// round 7
// speedup vs baseline: 1.6072x; 1.6072x over previous
#include <cuda_runtime.h>
#include <cuda_bf16.h>
#include <cstdint>

#define N_SRC 4096
#define D     256
#define TOT   8192
#define TILE  128
#define NT    (TOT / TILE)     // 64
#define HALF_NT (NT / 2)       // 32
#define CKB   128              // K-chunk bytes per row (128 int8)
#define NC    2                // 2 chunks of K=128
#define ROWB  144              // smem row stride: 128B data + 16B pad, conflict-free
#define MATB  (TILE * ROWB)    // 18432
#define STAGEB (2 * MATB)      // 36864
#define SQ_OFF (2 * STAGEB)    // 73728
#define SMEM_TOTAL (SQ_OFF + 2 * TILE * 4)   // 74752

#define QSCALE 32.0f           // x -> round(32x), clamp +-127; s^2 = 1/1024

// -------- device scratch --------
__device__ uint8_t g_q[(size_t)TOT * D];   // int8-quantized data (as bytes)
__device__ int    g_sqi[TOT];              // integer sum of squares (exact)
__device__ double g_acc;

// ---------------------------------------------------------------------------
// Kernel 1: fp32 -> int8 (q = round(32x), clamped) + exact int sumsq. Warp/row.
// ---------------------------------------------------------------------------
__global__ void prep_kernel(const float* __restrict__ src,
                            const float* __restrict__ tgt) {
    int lane = threadIdx.x & 31;
    int warp = threadIdx.x >> 5;
    int row  = blockIdx.x * 8 + warp;
    const float* base = (row < N_SRC) ? (src + (size_t)row * D)
                                      : (tgt + (size_t)(row - N_SRC) * D);
    float4 v0 = ((const float4*)base)[lane * 2];
    float4 v1 = ((const float4*)base)[lane * 2 + 1];
    float v[8] = {v0.x, v0.y, v0.z, v0.w, v1.x, v1.y, v1.z, v1.w};

    int s = 0;
    uint32_t p0 = 0, p1 = 0;
    #pragma unroll
    for (int i = 0; i < 8; i++) {
        int q = __float2int_rn(v[i] * QSCALE);
        q = max(-127, min(127, q));
        s += q * q;
        uint32_t b = (uint32_t)(uint8_t)(int8_t)q;
        if (i < 4) p0 |= b << (i * 8);
        else       p1 |= b << ((i - 4) * 8);
    }
    uint2 o; o.x = p0; o.y = p1;
    ((uint2*)(g_q + (size_t)row * D))[lane] = o;

    #pragma unroll
    for (int o2 = 16; o2; o2 >>= 1) s += __shfl_xor_sync(0xFFFFFFFFu, s, o2);
    if (lane == 0) g_sqi[row] = s;
    if (row == 0 && lane == 0) g_acc = 0.0;
}

// ---------------------------------------------------------------------------
// mma helpers
// ---------------------------------------------------------------------------
__device__ __forceinline__ void ldsm_x4(uint32_t& r0, uint32_t& r1,
                                        uint32_t& r2, uint32_t& r3,
                                        uint32_t addr) {
    asm volatile(
        "ldmatrix.sync.aligned.m8n8.x4.shared.b16 {%0,%1,%2,%3}, [%4];"
        : "=r"(r0), "=r"(r1), "=r"(r2), "=r"(r3)
        : "r"(addr));
}

__device__ __forceinline__ void mma_s8(int* c, const uint32_t* a,
                                       uint32_t b0, uint32_t b1) {
    asm volatile(
        "mma.sync.aligned.m16n8k32.row.col.s32.s8.s8.s32 "
        "{%0,%1,%2,%3}, {%4,%5,%6,%7}, {%8,%9}, {%0,%1,%2,%3};"
        : "+r"(c[0]), "+r"(c[1]), "+r"(c[2]), "+r"(c[3])
        : "r"(a[0]), "r"(a[1]), "r"(a[2]), "r"(a[3]), "r"(b0), "r"(b1));
}

__device__ __forceinline__ void cp16(uint32_t dst, const void* src) {
    asm volatile("cp.async.cg.shared.global [%0], [%1], 16;"
                 :: "r"(dst), "l"(src) : "memory");
}

__device__ __forceinline__ float ex2f(float x) {
    float y;
    asm("ex2.approx.ftz.f32 %0, %1;" : "=f"(y) : "f"(x));
    return y;
}

// ---------------------------------------------------------------------------
// Kernel 2: one CTA per 128x128 tile (upper block triangle), 8 warps (32x64
// warp tiles), s8 IMMA, cp.async 2-stage K-chunk pipeline, 2 CTAs/SM.
// Fragment layouts identical to the validated fp8/bf16 versions (k32 int8
// fragments == bf16 k16 fragments with "b16 elem" = byte pair).
// ---------------------------------------------------------------------------
__global__ void __launch_bounds__(256, 2)
mmd_kernel() {
    const int bi = blockIdx.x;
    const int bj = blockIdx.y;
    if (bj < bi) return;

    extern __shared__ __align__(128) char smem[];
    uint32_t sb = (uint32_t)__cvta_generic_to_shared(smem);

    const int tid  = threadIdx.x;
    const int lane = tid & 31;
    const int warp = tid >> 5;
    const int wm   = warp & 3;
    const int wn   = warp >> 2;

    int* sqA = (int*)(smem + SQ_OFF);
    int* sqB = sqA + TILE;
    if (tid < TILE)        sqA[tid] = g_sqi[bi * TILE + tid];
    else                   sqB[tid - TILE] = g_sqi[bj * TILE + (tid - TILE)];

    const uint8_t* Ag = g_q + (size_t)bi * TILE * D;
    const uint8_t* Bg = g_q + (size_t)bj * TILE * D;

    // ---- cp.async chunk loader: 2048 x 16B per chunk, 8 per thread ----
    auto load_chunk = [&](int c) {
        const int stage = c & 1;
        #pragma unroll
        for (int v = 0; v < 8; v++) {
            int u   = v * 256 + tid;      // 0..2047
            int mat = u >> 10;            // 0=A, 1=B
            int r   = (u >> 3) & 127;
            int vi  = u & 7;
            const uint8_t* g = (mat ? Bg : Ag) + (size_t)r * D + c * CKB + vi * 16;
            uint32_t dst = sb + stage * STAGEB + mat * MATB + r * ROWB + vi * 16;
            cp16(dst, g);
        }
    };

    // ---- ldmatrix addresses ----
    uint32_t addrA[2];
    #pragma unroll
    for (int mt = 0; mt < 2; mt++) {
        int r = wm * 32 + mt * 16 + (lane & 15);
        int coff = (lane >> 4) * 8;
        addrA[mt] = sb + (uint32_t)(r * ROWB + coff * 2);
    }
    uint32_t addrB[4];
    #pragma unroll
    for (int nt4 = 0; nt4 < 4; nt4++) {
        int quad = lane >> 3;
        int r = wn * 64 + nt4 * 16 + (lane & 7) + ((quad & 2) ? 8 : 0);
        int coff = (quad & 1) * 8;
        addrB[nt4] = sb + MATB + (uint32_t)(r * ROWB + coff * 2);
    }

    int c[2][8][4];
    #pragma unroll
    for (int mt = 0; mt < 2; mt++)
        #pragma unroll
        for (int nt = 0; nt < 8; nt++)
            #pragma unroll
            for (int e = 0; e < 4; e++) c[mt][nt][e] = 0;

    // ---- prologue: prefetch both chunks ----
    load_chunk(0);
    asm volatile("cp.async.commit_group;" ::: "memory");
    load_chunk(1);
    asm volatile("cp.async.commit_group;" ::: "memory");

    // ---- mainloop over 2 K-chunks ----
    #pragma unroll
    for (int ch = 0; ch < NC; ch++) {
        asm volatile("cp.async.wait_group 1;" ::: "memory");
        __syncthreads();

        const uint32_t soff = (ch & 1) * STAGEB;
        #pragma unroll
        for (int kk = 0; kk < 4; kk++) {           // 4 x k32 per chunk
            uint32_t kb = soff + (uint32_t)kk * 32;
            uint32_t a[2][4];
            ldsm_x4(a[0][0], a[0][1], a[0][2], a[0][3], addrA[0] + kb);
            ldsm_x4(a[1][0], a[1][1], a[1][2], a[1][3], addrA[1] + kb);
            uint32_t b[4][4];
            #pragma unroll
            for (int nt4 = 0; nt4 < 4; nt4++)
                ldsm_x4(b[nt4][0], b[nt4][1], b[nt4][2], b[nt4][3],
                        addrB[nt4] + kb);
            #pragma unroll
            for (int mt = 0; mt < 2; mt++)
                #pragma unroll
                for (int nt4 = 0; nt4 < 4; nt4++) {
                    mma_s8(c[mt][2 * nt4],     a[mt], b[nt4][0], b[nt4][1]);
                    mma_s8(c[mt][2 * nt4 + 1], a[mt], b[nt4][2], b[nt4][3]);
                }
        }
        __syncthreads();
        asm volatile("cp.async.commit_group;" ::: "memory");
    }

    // ---- epilogue: l2 = (sqa + sqb - 2*gram) / 1024, exact diagonal ----
    const float K_EX2 = -1.4426950408889634f / (16.0f * 1024.0f);
    const int g = lane >> 2;
    const int q = lane & 3;
    float wgt = (((bi < HALF_NT) == (bj < HALF_NT)) ? 1.0f : -1.0f)
              * ((bi == bj) ? 1.0f : 2.0f);

    // hoist the 4 distinct sqA values per thread (mt x e-high)
    int sqa_r[2][2];
    #pragma unroll
    for (int mt = 0; mt < 2; mt++)
        #pragma unroll
        for (int eh = 0; eh < 2; eh++)
            sqa_r[mt][eh] = sqA[wm * 32 + mt * 16 + g + eh * 8];

    float acc = 0.f;
    #pragma unroll
    for (int mt = 0; mt < 2; mt++) {
        #pragma unroll
        for (int nt = 0; nt < 8; nt++) {
            int sqb0 = sqB[wn * 64 + nt * 8 + q * 2];
            int sqb1 = sqB[wn * 64 + nt * 8 + q * 2 + 1];
            #pragma unroll
            for (int e = 0; e < 4; e++) {
                int iv = sqa_r[mt][e >> 1] + ((e & 1) ? sqb1 : sqb0)
                       - 2 * c[mt][nt][e];
                float u  = ex2f((float)iv * K_EX2);   // exp(-l2/16)
                float u2 = u * u, u4 = u2 * u2, u8 = u4 * u4, u16 = u8 * u8;
                acc += ((u + u2) + (u4 + u8)) + u16;
            }
        }
    }
    #pragma unroll
    for (int o = 16; o; o >>= 1) acc += __shfl_xor_sync(0xFFFFFFFFu, acc, o);
    if (lane == 0) atomicAdd(&g_acc, (double)(acc * wgt));
}

// ---------------------------------------------------------------------------
// Kernel 3: finalize scalar
// ---------------------------------------------------------------------------
__global__ void fin_kernel(float* out) {
    out[0] = (float)(g_acc * (1.0 / ((double)N_SRC * (double)N_SRC)));
}

extern "C" void kernel_launch(void* const* d_in, const int* in_sizes, int n_in,
                              void* d_out, int out_size) {
    const float* src = (const float*)d_in[0];
    const float* tgt = (const float*)d_in[1];
    float* out = (float*)d_out;

    cudaFuncSetAttribute(mmd_kernel,
                         cudaFuncAttributeMaxDynamicSharedMemorySize, SMEM_TOTAL);

    prep_kernel<<<TOT / 8, 256>>>(src, tgt);
    dim3 grid(NT, NT);
    mmd_kernel<<<grid, 256, SMEM_TOTAL>>>();
    fin_kernel<<<1, 1>>>(out);
}

// round 8
// speedup vs baseline: 1.6646x; 1.0357x over previous
#include <cuda_runtime.h>
#include <cuda_bf16.h>
#include <cstdint>

#define N_SRC 4096
#define D     256
#define TOT   8192
#define TILE  128
#define NT    (TOT / TILE)     // 64
#define HALF_NT (NT / 2)       // 32
#define CKB   128              // K-chunk bytes per row (128 int8)
#define NC    2                // 2 chunks of K=128
#define ROWB  144              // smem row stride: 128B data + 16B pad, conflict-free
#define MATB  (TILE * ROWB)    // 18432
#define STAGEB (2 * MATB)      // 36864
#define SQ_OFF (2 * STAGEB)    // 73728
#define SMEM_TOTAL (SQ_OFF + 2 * TILE * 4)   // 74752

#define QSCALE 32.0f           // x -> round(32x), clamp +-127; s^2 = 1/1024

// -------- device scratch --------
__device__ uint8_t g_q[(size_t)TOT * D];   // int8-quantized data (as bytes)
__device__ int    g_sqi[TOT];              // integer sum of squares (exact)
__device__ double g_acc;

// ---------------------------------------------------------------------------
// Kernel 1: fp32 -> int8 + exact int sumsq. Warp handles 2 rows (MLP=4).
// ---------------------------------------------------------------------------
__global__ void prep_kernel(const float* __restrict__ src,
                            const float* __restrict__ tgt) {
    int lane = threadIdx.x & 31;
    int warp = threadIdx.x >> 5;
    int row0 = blockIdx.x * 16 + warp * 2;

    const float* b0 = (row0 < N_SRC) ? (src + (size_t)row0 * D)
                                     : (tgt + (size_t)(row0 - N_SRC) * D);
    const float* b1 = (row0 + 1 < N_SRC) ? (src + (size_t)(row0 + 1) * D)
                                         : (tgt + (size_t)(row0 + 1 - N_SRC) * D);
    // issue all 4 loads before any use (MLP=4)
    float4 r0a = ((const float4*)b0)[lane * 2];
    float4 r0b = ((const float4*)b0)[lane * 2 + 1];
    float4 r1a = ((const float4*)b1)[lane * 2];
    float4 r1b = ((const float4*)b1)[lane * 2 + 1];

    #pragma unroll
    for (int rr = 0; rr < 2; rr++) {
        float4 va = rr ? r1a : r0a;
        float4 vb = rr ? r1b : r0b;
        float v[8] = {va.x, va.y, va.z, va.w, vb.x, vb.y, vb.z, vb.w};
        int s = 0;
        uint32_t p0 = 0, p1 = 0;
        #pragma unroll
        for (int i = 0; i < 8; i++) {
            int q = __float2int_rn(v[i] * QSCALE);
            q = max(-127, min(127, q));
            s += q * q;
            uint32_t b = (uint32_t)(uint8_t)(int8_t)q;
            if (i < 4) p0 |= b << (i * 8);
            else       p1 |= b << ((i - 4) * 8);
        }
        uint2 o; o.x = p0; o.y = p1;
        ((uint2*)(g_q + (size_t)(row0 + rr) * D))[lane] = o;
        #pragma unroll
        for (int o2 = 16; o2; o2 >>= 1) s += __shfl_xor_sync(0xFFFFFFFFu, s, o2);
        if (lane == 0) g_sqi[row0 + rr] = s;
    }
    if (row0 == 0 && lane == 0) g_acc = 0.0;
}

// ---------------------------------------------------------------------------
// mma / math helpers
// ---------------------------------------------------------------------------
__device__ __forceinline__ void ldsm_x4(uint32_t& r0, uint32_t& r1,
                                        uint32_t& r2, uint32_t& r3,
                                        uint32_t addr) {
    asm volatile(
        "ldmatrix.sync.aligned.m8n8.x4.shared.b16 {%0,%1,%2,%3}, [%4];"
        : "=r"(r0), "=r"(r1), "=r"(r2), "=r"(r3)
        : "r"(addr));
}

__device__ __forceinline__ void mma_s8(int* c, const uint32_t* a,
                                       uint32_t b0, uint32_t b1) {
    asm volatile(
        "mma.sync.aligned.m16n8k32.row.col.s32.s8.s8.s32 "
        "{%0,%1,%2,%3}, {%4,%5,%6,%7}, {%8,%9}, {%0,%1,%2,%3};"
        : "+r"(c[0]), "+r"(c[1]), "+r"(c[2]), "+r"(c[3])
        : "r"(a[0]), "r"(a[1]), "r"(a[2]), "r"(a[3]), "r"(b0), "r"(b1));
}

__device__ __forceinline__ void cp16(uint32_t dst, const void* src) {
    asm volatile("cp.async.cg.shared.global [%0], [%1], 16;"
                 :: "r"(dst), "l"(src) : "memory");
}

__device__ __forceinline__ float ex2f(float x) {
    float y;
    asm("ex2.approx.ftz.f32 %0, %1;" : "=f"(y) : "f"(x));
    return y;
}

// packed f32x2 (Blackwell base feature)
__device__ __forceinline__ uint64_t pk2(float a, float b) {
    uint64_t r; asm("mov.b64 %0, {%1, %2};" : "=l"(r) : "f"(a), "f"(b)); return r;
}
__device__ __forceinline__ uint64_t pmul(uint64_t a, uint64_t b) {
    uint64_t r; asm("mul.rn.f32x2 %0, %1, %2;" : "=l"(r) : "l"(a), "l"(b)); return r;
}
__device__ __forceinline__ uint64_t padd(uint64_t a, uint64_t b) {
    uint64_t r; asm("add.rn.f32x2 %0, %1, %2;" : "=l"(r) : "l"(a), "l"(b)); return r;
}

// ---------------------------------------------------------------------------
// Kernel 2: one CTA per 128x128 tile (upper block triangle), 8 warps (32x64
// warp tiles), s8 IMMA, cp.async 2-stage K-chunk pipeline, 2 CTAs/SM.
// ---------------------------------------------------------------------------
__global__ void __launch_bounds__(256, 2)
mmd_kernel() {
    const int bi = blockIdx.x;
    const int bj = blockIdx.y;
    if (bj < bi) return;

    extern __shared__ __align__(128) char smem[];
    uint32_t sb = (uint32_t)__cvta_generic_to_shared(smem);

    const int tid  = threadIdx.x;
    const int lane = tid & 31;
    const int warp = tid >> 5;
    const int wm   = warp & 3;
    const int wn   = warp >> 2;

    int* sqA = (int*)(smem + SQ_OFF);
    int* sqB = sqA + TILE;
    if (tid < TILE)        sqA[tid] = g_sqi[bi * TILE + tid];
    else                   sqB[tid - TILE] = g_sqi[bj * TILE + (tid - TILE)];

    const uint8_t* Ag = g_q + (size_t)bi * TILE * D;
    const uint8_t* Bg = g_q + (size_t)bj * TILE * D;

    // ---- cp.async chunk loader: 2048 x 16B per chunk, 8 per thread ----
    auto load_chunk = [&](int c) {
        const int stage = c & 1;
        #pragma unroll
        for (int v = 0; v < 8; v++) {
            int u   = v * 256 + tid;      // 0..2047
            int mat = u >> 10;            // 0=A, 1=B
            int r   = (u >> 3) & 127;
            int vi  = u & 7;
            const uint8_t* g = (mat ? Bg : Ag) + (size_t)r * D + c * CKB + vi * 16;
            uint32_t dst = sb + stage * STAGEB + mat * MATB + r * ROWB + vi * 16;
            cp16(dst, g);
        }
    };

    // ---- ldmatrix addresses ----
    uint32_t addrA[2];
    #pragma unroll
    for (int mt = 0; mt < 2; mt++) {
        int r = wm * 32 + mt * 16 + (lane & 15);
        int coff = (lane >> 4) * 8;
        addrA[mt] = sb + (uint32_t)(r * ROWB + coff * 2);
    }
    uint32_t addrB[4];
    #pragma unroll
    for (int nt4 = 0; nt4 < 4; nt4++) {
        int quad = lane >> 3;
        int r = wn * 64 + nt4 * 16 + (lane & 7) + ((quad & 2) ? 8 : 0);
        int coff = (quad & 1) * 8;
        addrB[nt4] = sb + MATB + (uint32_t)(r * ROWB + coff * 2);
    }

    int c[2][8][4];
    #pragma unroll
    for (int mt = 0; mt < 2; mt++)
        #pragma unroll
        for (int nt = 0; nt < 8; nt++)
            #pragma unroll
            for (int e = 0; e < 4; e++) c[mt][nt][e] = 0;

    // ---- prologue: prefetch both chunks ----
    load_chunk(0);
    asm volatile("cp.async.commit_group;" ::: "memory");
    load_chunk(1);
    asm volatile("cp.async.commit_group;" ::: "memory");

    // ---- mainloop over 2 K-chunks ----
    #pragma unroll
    for (int ch = 0; ch < NC; ch++) {
        asm volatile("cp.async.wait_group 1;" ::: "memory");
        __syncthreads();

        const uint32_t soff = (ch & 1) * STAGEB;
        #pragma unroll
        for (int kk = 0; kk < 4; kk++) {           // 4 x k32 per chunk
            uint32_t kb = soff + (uint32_t)kk * 32;
            uint32_t a[2][4];
            ldsm_x4(a[0][0], a[0][1], a[0][2], a[0][3], addrA[0] + kb);
            ldsm_x4(a[1][0], a[1][1], a[1][2], a[1][3], addrA[1] + kb);
            uint32_t b[4][4];
            #pragma unroll
            for (int nt4 = 0; nt4 < 4; nt4++)
                ldsm_x4(b[nt4][0], b[nt4][1], b[nt4][2], b[nt4][3],
                        addrB[nt4] + kb);
            #pragma unroll
            for (int mt = 0; mt < 2; mt++)
                #pragma unroll
                for (int nt4 = 0; nt4 < 4; nt4++) {
                    mma_s8(c[mt][2 * nt4],     a[mt], b[nt4][0], b[nt4][1]);
                    mma_s8(c[mt][2 * nt4 + 1], a[mt], b[nt4][2], b[nt4][3]);
                }
        }
        __syncthreads();
        asm volatile("cp.async.commit_group;" ::: "memory");
    }

    // ---- epilogue: l2 = (sqa + sqb - 2*gram)/1024; packed f32x2 polynomial ----
    const float K_EX2 = -1.4426950408889634f / (16.0f * 1024.0f);
    const int g = lane >> 2;
    const int q = lane & 3;
    float wgt = (((bi < HALF_NT) == (bj < HALF_NT)) ? 1.0f : -1.0f)
              * ((bi == bj) ? 1.0f : 2.0f);

    int sqa_r[2][2];
    #pragma unroll
    for (int mt = 0; mt < 2; mt++)
        #pragma unroll
        for (int eh = 0; eh < 2; eh++)
            sqa_r[mt][eh] = sqA[wm * 32 + mt * 16 + g + eh * 8];

    uint64_t acc2 = pk2(0.f, 0.f);
    #pragma unroll
    for (int nt = 0; nt < 8; nt++) {
        int sqb0 = sqB[wn * 64 + nt * 8 + q * 2];
        int sqb1 = sqB[wn * 64 + nt * 8 + q * 2 + 1];
        #pragma unroll
        for (int mt = 0; mt < 2; mt++) {
            #pragma unroll
            for (int eh = 0; eh < 2; eh++) {   // element pair (col q*2, q*2+1)
                int sqa = sqa_r[mt][eh];
                int iv0 = sqa + sqb0 - 2 * c[mt][nt][eh * 2];
                int iv1 = sqa + sqb1 - 2 * c[mt][nt][eh * 2 + 1];
                float u0 = ex2f((float)iv0 * K_EX2);   // exp(-l2/16)
                float u1 = ex2f((float)iv1 * K_EX2);
                uint64_t U  = pk2(u0, u1);
                uint64_t U2 = pmul(U, U);
                uint64_t U4 = pmul(U2, U2);
                uint64_t U8 = pmul(U4, U4);
                uint64_t U16 = pmul(U8, U8);
                uint64_t S = padd(padd(U, U2), padd(U4, U8));
                acc2 = padd(acc2, padd(S, U16));
            }
        }
    }
    uint32_t lo, hi;
    asm("mov.b64 {%0, %1}, %2;" : "=r"(lo), "=r"(hi) : "l"(acc2));
    float acc = __uint_as_float(lo) + __uint_as_float(hi);
    #pragma unroll
    for (int o = 16; o; o >>= 1) acc += __shfl_xor_sync(0xFFFFFFFFu, acc, o);
    if (lane == 0) atomicAdd(&g_acc, (double)(acc * wgt));
}

// ---------------------------------------------------------------------------
// Kernel 3: finalize scalar
// ---------------------------------------------------------------------------
__global__ void fin_kernel(float* out) {
    out[0] = (float)(g_acc * (1.0 / ((double)N_SRC * (double)N_SRC)));
}

extern "C" void kernel_launch(void* const* d_in, const int* in_sizes, int n_in,
                              void* d_out, int out_size) {
    const float* src = (const float*)d_in[0];
    const float* tgt = (const float*)d_in[1];
    float* out = (float*)d_out;

    cudaFuncSetAttribute(mmd_kernel,
                         cudaFuncAttributeMaxDynamicSharedMemorySize, SMEM_TOTAL);

    prep_kernel<<<TOT / 16, 256>>>(src, tgt);
    dim3 grid(NT, NT);
    mmd_kernel<<<grid, 256, SMEM_TOTAL>>>();
    fin_kernel<<<1, 1>>>(out);
}

// round 9
// speedup vs baseline: 1.6751x; 1.0063x over previous
#include <cuda_runtime.h>
#include <cuda_bf16.h>
#include <cstdint>

#define N_SRC 4096
#define D     256
#define TOT   8192
#define TILE  128
#define NT    (TOT / TILE)     // 64
#define HALF_NT (NT / 2)       // 32
#define CKB   128              // K-chunk bytes per row (128 int8)
#define NC    2                // 2 chunks of K=128
#define ROWB  144              // smem row stride: 128B data + 16B pad, conflict-free
#define MATB  (TILE * ROWB)    // 18432
#define STAGEB (2 * MATB)      // 36864
#define SQ_OFF (2 * STAGEB)    // 73728
#define RED_OFF (SQ_OFF + 2 * TILE * 4)      // 74752 (8 floats, warp partials)
#define SMEM_TOTAL (RED_OFF + 8 * 4)         // 74784

#define QSCALE 32.0f           // x -> round(32x), clamp +-127; s^2 = 1/1024

// -------- device scratch --------
__device__ uint8_t g_q[(size_t)TOT * D];   // int8-quantized data (as bytes)
__device__ int    g_sqi[TOT];              // integer sum of squares (exact)
__device__ double g_acc;

// ---------------------------------------------------------------------------
// Kernel 1: fp32 -> int8 + exact int sumsq. Warp handles 4 rows, MLP=8.
// ---------------------------------------------------------------------------
__global__ void prep_kernel(const float* __restrict__ src,
                            const float* __restrict__ tgt) {
    int lane = threadIdx.x & 31;
    int warp = threadIdx.x >> 5;
    int row0 = blockIdx.x * 32 + warp * 4;

    // issue all 8 loads before any use (MLP=8)
    float4 la[4], lb[4];
    #pragma unroll
    for (int rr = 0; rr < 4; rr++) {
        int row = row0 + rr;
        const float* b = (row < N_SRC) ? (src + (size_t)row * D)
                                       : (tgt + (size_t)(row - N_SRC) * D);
        la[rr] = ((const float4*)b)[lane * 2];
        lb[rr] = ((const float4*)b)[lane * 2 + 1];
    }

    #pragma unroll
    for (int rr = 0; rr < 4; rr++) {
        float v[8] = {la[rr].x, la[rr].y, la[rr].z, la[rr].w,
                      lb[rr].x, lb[rr].y, lb[rr].z, lb[rr].w};
        int s = 0;
        uint32_t p0 = 0, p1 = 0;
        #pragma unroll
        for (int i = 0; i < 8; i++) {
            int q = __float2int_rn(v[i] * QSCALE);
            q = max(-127, min(127, q));
            s += q * q;
            uint32_t b = (uint32_t)(uint8_t)(int8_t)q;
            if (i < 4) p0 |= b << (i * 8);
            else       p1 |= b << ((i - 4) * 8);
        }
        uint2 o; o.x = p0; o.y = p1;
        ((uint2*)(g_q + (size_t)(row0 + rr) * D))[lane] = o;
        #pragma unroll
        for (int o2 = 16; o2; o2 >>= 1) s += __shfl_xor_sync(0xFFFFFFFFu, s, o2);
        if (lane == 0) g_sqi[row0 + rr] = s;
    }
    if (row0 == 0 && lane == 0) g_acc = 0.0;
}

// ---------------------------------------------------------------------------
// mma / math helpers
// ---------------------------------------------------------------------------
__device__ __forceinline__ void ldsm_x4(uint32_t& r0, uint32_t& r1,
                                        uint32_t& r2, uint32_t& r3,
                                        uint32_t addr) {
    asm volatile(
        "ldmatrix.sync.aligned.m8n8.x4.shared.b16 {%0,%1,%2,%3}, [%4];"
        : "=r"(r0), "=r"(r1), "=r"(r2), "=r"(r3)
        : "r"(addr));
}

__device__ __forceinline__ void mma_s8(int* c, const uint32_t* a,
                                       uint32_t b0, uint32_t b1) {
    asm volatile(
        "mma.sync.aligned.m16n8k32.row.col.s32.s8.s8.s32 "
        "{%0,%1,%2,%3}, {%4,%5,%6,%7}, {%8,%9}, {%0,%1,%2,%3};"
        : "+r"(c[0]), "+r"(c[1]), "+r"(c[2]), "+r"(c[3])
        : "r"(a[0]), "r"(a[1]), "r"(a[2]), "r"(a[3]), "r"(b0), "r"(b1));
}

__device__ __forceinline__ void cp16(uint32_t dst, const void* src) {
    asm volatile("cp.async.cg.shared.global [%0], [%1], 16;"
                 :: "r"(dst), "l"(src) : "memory");
}

__device__ __forceinline__ float ex2f(float x) {
    float y;
    asm("ex2.approx.ftz.f32 %0, %1;" : "=f"(y) : "f"(x));
    return y;
}

// packed f32x2 (Blackwell base feature)
__device__ __forceinline__ uint64_t pk2(float a, float b) {
    uint64_t r; asm("mov.b64 %0, {%1, %2};" : "=l"(r) : "f"(a), "f"(b)); return r;
}
__device__ __forceinline__ uint64_t pmul(uint64_t a, uint64_t b) {
    uint64_t r; asm("mul.rn.f32x2 %0, %1, %2;" : "=l"(r) : "l"(a), "l"(b)); return r;
}
__device__ __forceinline__ uint64_t padd(uint64_t a, uint64_t b) {
    uint64_t r; asm("add.rn.f32x2 %0, %1, %2;" : "=l"(r) : "l"(a), "l"(b)); return r;
}

// ---------------------------------------------------------------------------
// Kernel 2: one CTA per 128x128 tile (upper block triangle), 8 warps (32x64
// warp tiles), s8 IMMA, cp.async 2-stage K-chunk pipeline, 2 CTAs/SM.
// Block-level reduction -> ONE fp64 atomic per CTA.
// ---------------------------------------------------------------------------
__global__ void __launch_bounds__(256, 2)
mmd_kernel() {
    const int bi = blockIdx.x;
    const int bj = blockIdx.y;
    if (bj < bi) return;

    extern __shared__ __align__(128) char smem[];
    uint32_t sb = (uint32_t)__cvta_generic_to_shared(smem);

    const int tid  = threadIdx.x;
    const int lane = tid & 31;
    const int warp = tid >> 5;
    const int wm   = warp & 3;
    const int wn   = warp >> 2;

    int* sqA = (int*)(smem + SQ_OFF);
    int* sqB = sqA + TILE;
    float* red = (float*)(smem + RED_OFF);
    if (tid < TILE)        sqA[tid] = g_sqi[bi * TILE + tid];
    else                   sqB[tid - TILE] = g_sqi[bj * TILE + (tid - TILE)];

    const uint8_t* Ag = g_q + (size_t)bi * TILE * D;
    const uint8_t* Bg = g_q + (size_t)bj * TILE * D;

    // ---- cp.async chunk loader: 2048 x 16B per chunk, 8 per thread ----
    auto load_chunk = [&](int c) {
        const int stage = c & 1;
        #pragma unroll
        for (int v = 0; v < 8; v++) {
            int u   = v * 256 + tid;      // 0..2047
            int mat = u >> 10;            // 0=A, 1=B
            int r   = (u >> 3) & 127;
            int vi  = u & 7;
            const uint8_t* g = (mat ? Bg : Ag) + (size_t)r * D + c * CKB + vi * 16;
            uint32_t dst = sb + stage * STAGEB + mat * MATB + r * ROWB + vi * 16;
            cp16(dst, g);
        }
    };

    // ---- ldmatrix addresses ----
    uint32_t addrA[2];
    #pragma unroll
    for (int mt = 0; mt < 2; mt++) {
        int r = wm * 32 + mt * 16 + (lane & 15);
        int coff = (lane >> 4) * 8;
        addrA[mt] = sb + (uint32_t)(r * ROWB + coff * 2);
    }
    uint32_t addrB[4];
    #pragma unroll
    for (int nt4 = 0; nt4 < 4; nt4++) {
        int quad = lane >> 3;
        int r = wn * 64 + nt4 * 16 + (lane & 7) + ((quad & 2) ? 8 : 0);
        int coff = (quad & 1) * 8;
        addrB[nt4] = sb + MATB + (uint32_t)(r * ROWB + coff * 2);
    }

    int c[2][8][4];
    #pragma unroll
    for (int mt = 0; mt < 2; mt++)
        #pragma unroll
        for (int nt = 0; nt < 8; nt++)
            #pragma unroll
            for (int e = 0; e < 4; e++) c[mt][nt][e] = 0;

    // ---- prologue: prefetch both chunks ----
    load_chunk(0);
    asm volatile("cp.async.commit_group;" ::: "memory");
    load_chunk(1);
    asm volatile("cp.async.commit_group;" ::: "memory");

    // ---- mainloop over 2 K-chunks ----
    #pragma unroll
    for (int ch = 0; ch < NC; ch++) {
        asm volatile("cp.async.wait_group 1;" ::: "memory");
        __syncthreads();

        const uint32_t soff = (ch & 1) * STAGEB;
        #pragma unroll
        for (int kk = 0; kk < 4; kk++) {           // 4 x k32 per chunk
            uint32_t kb = soff + (uint32_t)kk * 32;
            uint32_t a[2][4];
            ldsm_x4(a[0][0], a[0][1], a[0][2], a[0][3], addrA[0] + kb);
            ldsm_x4(a[1][0], a[1][1], a[1][2], a[1][3], addrA[1] + kb);
            uint32_t b[4][4];
            #pragma unroll
            for (int nt4 = 0; nt4 < 4; nt4++)
                ldsm_x4(b[nt4][0], b[nt4][1], b[nt4][2], b[nt4][3],
                        addrB[nt4] + kb);
            #pragma unroll
            for (int mt = 0; mt < 2; mt++)
                #pragma unroll
                for (int nt4 = 0; nt4 < 4; nt4++) {
                    mma_s8(c[mt][2 * nt4],     a[mt], b[nt4][0], b[nt4][1]);
                    mma_s8(c[mt][2 * nt4 + 1], a[mt], b[nt4][2], b[nt4][3]);
                }
        }
        __syncthreads();
        asm volatile("cp.async.commit_group;" ::: "memory");
    }

    // ---- epilogue: l2 = (sqa + sqb - 2*gram)/1024; packed f32x2 polynomial ----
    const float K_EX2 = -1.4426950408889634f / (16.0f * 1024.0f);
    const int g = lane >> 2;
    const int q = lane & 3;

    int sqa_r[2][2];
    #pragma unroll
    for (int mt = 0; mt < 2; mt++)
        #pragma unroll
        for (int eh = 0; eh < 2; eh++)
            sqa_r[mt][eh] = sqA[wm * 32 + mt * 16 + g + eh * 8];

    uint64_t acc2 = pk2(0.f, 0.f);
    #pragma unroll
    for (int nt = 0; nt < 8; nt++) {
        int sqb0 = sqB[wn * 64 + nt * 8 + q * 2];
        int sqb1 = sqB[wn * 64 + nt * 8 + q * 2 + 1];
        #pragma unroll
        for (int mt = 0; mt < 2; mt++) {
            #pragma unroll
            for (int eh = 0; eh < 2; eh++) {   // element pair (col q*2, q*2+1)
                int sqa = sqa_r[mt][eh];
                int iv0 = sqa + sqb0 - 2 * c[mt][nt][eh * 2];
                int iv1 = sqa + sqb1 - 2 * c[mt][nt][eh * 2 + 1];
                float u0 = ex2f((float)iv0 * K_EX2);   // exp(-l2/16)
                float u1 = ex2f((float)iv1 * K_EX2);
                uint64_t U  = pk2(u0, u1);
                uint64_t U2 = pmul(U, U);
                uint64_t U4 = pmul(U2, U2);
                uint64_t U8 = pmul(U4, U4);
                uint64_t U16 = pmul(U8, U8);
                uint64_t S = padd(padd(U, U2), padd(U4, U8));
                acc2 = padd(acc2, padd(S, U16));
            }
        }
    }
    uint32_t lo, hi;
    asm("mov.b64 {%0, %1}, %2;" : "=r"(lo), "=r"(hi) : "l"(acc2));
    float acc = __uint_as_float(lo) + __uint_as_float(hi);
    #pragma unroll
    for (int o = 16; o; o >>= 1) acc += __shfl_xor_sync(0xFFFFFFFFu, acc, o);

    // ---- block reduce: 8 warp partials -> ONE fp64 atomic per CTA ----
    if (lane == 0) red[warp] = acc;
    __syncthreads();
    if (warp == 0 && lane == 0) {
        float t = red[0] + red[1] + red[2] + red[3]
                + red[4] + red[5] + red[6] + red[7];
        float wgt = (((bi < HALF_NT) == (bj < HALF_NT)) ? 1.0f : -1.0f)
                  * ((bi == bj) ? 1.0f : 2.0f);
        atomicAdd(&g_acc, (double)(t * wgt));
    }
}

// ---------------------------------------------------------------------------
// Kernel 3: finalize scalar
// ---------------------------------------------------------------------------
__global__ void fin_kernel(float* out) {
    out[0] = (float)(g_acc * (1.0 / ((double)N_SRC * (double)N_SRC)));
}

extern "C" void kernel_launch(void* const* d_in, const int* in_sizes, int n_in,
                              void* d_out, int out_size) {
    const float* src = (const float*)d_in[0];
    const float* tgt = (const float*)d_in[1];
    float* out = (float*)d_out;

    cudaFuncSetAttribute(mmd_kernel,
                         cudaFuncAttributeMaxDynamicSharedMemorySize, SMEM_TOTAL);

    prep_kernel<<<TOT / 32, 256>>>(src, tgt);
    dim3 grid(NT, NT);
    mmd_kernel<<<grid, 256, SMEM_TOTAL>>>();
    fin_kernel<<<1, 1>>>(out);
}